// round 15
// baseline (speedup 1.0000x reference)
#include <cuda_runtime.h>
#include <cuda_fp16.h>
#include <cstdint>
#include <cstddef>

#define S_LEN 512
#define BATCH 64
#define HID   1024
#define NG    4096            // 4*HID
#define MTOT  (S_LEN*BATCH)   // 32768
#define GRID  128             // persistent CTAs (HID/8)
#define PTHR  512             // persist threads: 16 warps (4/SMSP)

// persist SMEM (fp16 W + fp16 A chunks + fp32 partials)
#define BH_STR 532                        // W row stride in 32-bit words (512+20; %32==20)
#define ACH_STR 20                        // A chunk row stride in words (16+4; %32==20)
#define ACH_WARP (32 * ACH_STR)           // 640 words per warp chunk buffer (32 rows)
#define PART_WARP 1024                    // fp32 partials per warp
#define SM_BW_BYTES (32 * BH_STR * 4)     // 68096
#define SM_ACH_OFF  SM_BW_BYTES
#define SM_ACH_BYTES (16 * ACH_WARP * 4)  // 40960
#define SM_PART_OFF (SM_ACH_OFF + SM_ACH_BYTES)       // 109056
#define SM_TOTAL_P  (SM_PART_OFF + 16 * PART_WARP * 4) // 174592 (~170.5KB)

// gemmA v3: CTA tile 128x128, 4 stages x (As[128][36] + Bs[128][36])
#define GA_STGF ((128 + 128) * 36)
#define GA_SMEM (4 * GA_STGF * 4)

// ---- scratch (device globals; no runtime allocation) ----
__device__ float  g_gx[(size_t)MTOT * NG];   // precomputed x@W_ih^T + b
__device__ float  g_h[2][BATCH * HID];       // fp32 hidden (for ar_step)
__device__ __half g_hh[2][BATCH * HID];      // fp16 hidden (persist datapath)
__device__ float  g_c[BATCH * HID];          // cell state (fp32)
__device__ float  g_b[NG];                   // b_ih + b_hh
__device__ float  g_wsum[(size_t)NG * HID];  // W_ih + W_hh (AR steps)
__device__ unsigned g_bar;                   // grid barrier counter

// ---- helpers ----
__device__ __forceinline__ float tfr(float f) {
    unsigned u;
    asm("cvt.rna.tf32.f32 %0, %1;" : "=r"(u) : "f"(f));
    return __uint_as_float(u);
}

__device__ __forceinline__ void mma_tf32(float c[4], const unsigned a[4], const unsigned b[2]) {
    asm volatile(
        "mma.sync.aligned.m16n8k8.row.col.f32.tf32.tf32.f32 "
        "{%0,%1,%2,%3}, {%4,%5,%6,%7}, {%8,%9}, {%0,%1,%2,%3};\n"
        : "+f"(c[0]), "+f"(c[1]), "+f"(c[2]), "+f"(c[3])
        : "r"(a[0]), "r"(a[1]), "r"(a[2]), "r"(a[3]), "r"(b[0]), "r"(b[1]));
}

__device__ __forceinline__ void mma_f16(float c[4], const unsigned a[4], const unsigned b[2]) {
    asm volatile(
        "mma.sync.aligned.m16n8k16.row.col.f32.f16.f16.f32 "
        "{%0,%1,%2,%3}, {%4,%5,%6,%7}, {%8,%9}, {%0,%1,%2,%3};\n"
        : "+f"(c[0]), "+f"(c[1]), "+f"(c[2]), "+f"(c[3])
        : "r"(a[0]), "r"(a[1]), "r"(a[2]), "r"(a[3]), "r"(b[0]), "r"(b[1]));
}

#define CP_ASYNC16(dst_u32, src) \
    asm volatile("cp.async.cg.shared.global [%0], [%1], 16;\n" :: "r"(dst_u32), "l"(src))
#define CP_COMMIT() asm volatile("cp.async.commit_group;\n" ::: "memory")
#define CP_WAIT2()  asm volatile("cp.async.wait_group 2;\n" ::: "memory")

// ============================================================================
// prep: biases, Wsum, h0 (fp32 + fp16), c0, barrier=0
// ============================================================================
__global__ void prep_kernel(const float* __restrict__ W_ih, const float* __restrict__ W_hh,
                            const float* __restrict__ b_ih, const float* __restrict__ b_hh,
                            const float* __restrict__ hx0,  const float* __restrict__ cx0) {
    int idx = blockIdx.x * blockDim.x + threadIdx.x;
    if (idx == 0) g_bar = 0;
    if (idx < NG * HID) g_wsum[idx] = W_ih[idx] + W_hh[idx];
    if (idx < NG)       g_b[idx]    = b_ih[idx] + b_hh[idx];
    if (idx < BATCH * HID) {
        g_h[0][idx]  = hx0[idx];
        g_hh[0][idx] = __float2half(hx0[idx]);
        g_c[idx]     = cx0[idx];
    }
}

// ============================================================================
// gemmA v3 (unchanged, R11-proven): CTA tile 128x128, 4-stage cp.async, tf32.
// ============================================================================
__global__ __launch_bounds__(256) void gemmA_kernel(const float* __restrict__ X,
                                                    const float* __restrict__ W) {
    extern __shared__ float gsm[];

    const int tid  = threadIdx.x;
    const int wid  = tid >> 5, lane = tid & 31;
    const int wm   = wid >> 2;
    const int wn   = wid & 3;
    const int m0   = blockIdx.y * 128;
    const int n0   = blockIdx.x * 128;

    const float* Ag = X + (size_t)m0 * HID;
    const float* Bg = W + (size_t)n0 * HID;

    int ar_[4], af_[4];
    #pragma unroll
    for (int i = 0; i < 4; i++) { int l = tid + i * 256; ar_[i] = l >> 3; af_[i] = l & 7; }

    auto issue = [&](int kc) {
        int s = kc & 3;
        float* as = gsm + s * GA_STGF;
        float* bs = as + 128 * 36;
        const int k0 = kc * 32;
        #pragma unroll
        for (int i = 0; i < 4; i++) {
            unsigned dst = (unsigned)__cvta_generic_to_shared(&as[ar_[i] * 36 + af_[i] * 4]);
            CP_ASYNC16(dst, Ag + (size_t)ar_[i] * HID + k0 + af_[i] * 4);
        }
        #pragma unroll
        for (int i = 0; i < 4; i++) {
            unsigned dst = (unsigned)__cvta_generic_to_shared(&bs[ar_[i] * 36 + af_[i] * 4]);
            CP_ASYNC16(dst, Bg + (size_t)ar_[i] * HID + k0 + af_[i] * 4);
        }
        CP_COMMIT();
    };

    float c[4][4][4];
    #pragma unroll
    for (int mt = 0; mt < 4; mt++)
        #pragma unroll
        for (int nt = 0; nt < 4; nt++)
            #pragma unroll
            for (int r = 0; r < 4; r++) c[mt][nt][r] = 0.f;

    issue(0); issue(1); issue(2);

    for (int kc = 0; kc < 32; kc++) {
        CP_WAIT2();
        __syncthreads();
        if (kc + 3 < 32) issue(kc + 3);
        else CP_COMMIT();

        const float* as = gsm + (kc & 3) * GA_STGF;
        const float* bs = as + 128 * 36;

        #pragma unroll
        for (int kk = 0; kk < 4; kk++) {
            const int k8 = kk * 8;
            unsigned a[4][4], b[4][2];
            #pragma unroll
            for (int mt = 0; mt < 4; mt++) {
                int r0 = wm * 64 + mt * 16 + (lane >> 2);
                a[mt][0] = __float_as_uint(tfr(as[r0 * 36 + k8 + (lane & 3)]));
                a[mt][1] = __float_as_uint(tfr(as[(r0 + 8) * 36 + k8 + (lane & 3)]));
                a[mt][2] = __float_as_uint(tfr(as[r0 * 36 + k8 + (lane & 3) + 4]));
                a[mt][3] = __float_as_uint(tfr(as[(r0 + 8) * 36 + k8 + (lane & 3) + 4]));
            }
            #pragma unroll
            for (int nt = 0; nt < 4; nt++) {
                int rn = wn * 32 + nt * 8 + (lane >> 2);
                b[nt][0] = __float_as_uint(tfr(bs[rn * 36 + k8 + (lane & 3)]));
                b[nt][1] = __float_as_uint(tfr(bs[rn * 36 + k8 + (lane & 3) + 4]));
            }
            #pragma unroll
            for (int mt = 0; mt < 4; mt++)
                #pragma unroll
                for (int nt = 0; nt < 4; nt++)
                    mma_tf32(c[mt][nt], a[mt], b[nt]);
        }
    }

    #pragma unroll
    for (int mt = 0; mt < 4; mt++) {
        #pragma unroll
        for (int nt = 0; nt < 4; nt++) {
            int row = m0 + wm * 64 + mt * 16 + (lane >> 2);
            int col = n0 + wn * 32 + nt * 8 + 2 * (lane & 3);
            float b0 = g_b[col], b1 = g_b[col + 1];
            g_gx[(size_t)row * NG + col]           = c[mt][nt][0] + b0;
            g_gx[(size_t)row * NG + col + 1]       = c[mt][nt][1] + b1;
            g_gx[(size_t)(row + 8) * NG + col]     = c[mt][nt][2] + b0;
            g_gx[(size_t)(row + 8) * NG + col + 1] = c[mt][nt][3] + b1;
        }
    }
}

// ============================================================================
// persist v5: fp16 datapath, 16 warps. Warp w: kslice = w>>1 (K range
// [kslice*128, +128)), mhalf = w&1 (M rows [mhalf*32, +32)). Private chunk
// staging, shared W in SMEM, k-slice reduce order identical to v4.
// ============================================================================
__global__ __launch_bounds__(PTHR) void persist_kernel(const float* __restrict__ Whh) {
    extern __shared__ float sm[];
    uint32_t* Bw   = reinterpret_cast<uint32_t*>(sm);                 // W fp16: [32][BH_STR] words
    uint32_t* Aw   = reinterpret_cast<uint32_t*>(
                         reinterpret_cast<char*>(sm) + SM_ACH_OFF);   // 16 x [32][ACH_STR] words
    float*    Part = reinterpret_cast<float*>(
                         reinterpret_cast<char*>(sm) + SM_PART_OFF);  // 16 x PART_WARP fp32

    const int tid = threadIdx.x, wid = tid >> 5, lane = tid & 31;
    const int j0 = blockIdx.x * 8;
    const int kslice = wid >> 1;            // 0..7
    const int mhalf  = wid & 1;             // 0..1
    const int kbase  = kslice * 128;
    const int rbase  = mhalf * 32;
    uint32_t* myAw = Aw + wid * ACH_WARP;
    float*    myP  = Part + wid * PART_WARP;

    // ---- prologue: W slice -> fp16 SMEM, rows rn = gate*8+jj, k word-packed ----
    for (int i = tid; i < 32 * 512; i += PTHR) {     // 16384 words
        int rn = i >> 9, w = i & 511;
        int gate = rn >> 3, jj = rn & 7;
        const float* wp = Whh + (size_t)(gate * HID + j0 + jj) * HID + w * 2;
        __half2 hv = __floats2half2_rn(wp[0], wp[1]);
        Bw[rn * BH_STR + w] = *reinterpret_cast<uint32_t*>(&hv);
    }
    __syncthreads();

    // reduce-phase position mapping (1 position per thread)
    int mm, jjv, mho, mtl, base_r, base_ln;
    {
        int p  = tid;                         // 0..511
        int mt4 = p >> 7, r = (p >> 5) & 3, ln = p & 31;
        mm  = mt4 * 16 + (ln >> 2) + 8 * (r >> 1);    // 0..63
        jjv = 2 * (ln & 3) + (r & 1);                 // 0..7
        mho = mm >> 5;                                // M-half of this output
        mtl = (mm >> 4) & 1;                          // warp-local mt tile
        base_r = r; base_ln = ln;
    }
    int base_pw[4];
    #pragma unroll
    for (int nt = 0; nt < 4; nt++)
        base_pw[nt] = ((mtl * 4 + nt) * 4 + base_r) * 32 + base_ln;

    for (int t = 0; t < S_LEN; t++) {
        const __half* __restrict__ hin   = g_hh[t & 1];
        __half*       __restrict__ hhout = g_hh[(t + 1) & 1];
        float*        __restrict__ hfout = g_h[(t + 1) & 1];
        const float*  __restrict__ gx_t  = g_gx + (size_t)t * BATCH * NG;

        // ---- per-warp GEMM over own (K-slice, M-half); no block syncs ----
        uint4 pf[4];
        auto ldchunk = [&](int cc) {
            #pragma unroll
            for (int i = 0; i < 4; i++) {
                int u = lane + 32 * i;
                int r = u >> 2, w4 = u & 3;          // 32 rows x 4 uint4 (32 halves)
                pf[i] = __ldcg(reinterpret_cast<const uint4*>(
                    hin + (size_t)(rbase + r) * HID + kbase + cc * 32 + w4 * 8));
            }
        };
        auto stchunk = [&]() {
            #pragma unroll
            for (int i = 0; i < 4; i++) {
                int u = lane + 32 * i;
                int r = u >> 2, w4 = u & 3;
                *reinterpret_cast<uint4*>(myAw + r * ACH_STR + w4 * 4) = pf[i];
            }
        };

        ldchunk(0);    // issue h loads first (longest latency)

        // prefetch gx + c for the reduce phase (hidden under GEMM)
        float gxr[4], cr;
        {
            const float* gp = gx_t + (size_t)mm * NG + j0 + jjv;
            gxr[0] = gp[0 * HID];
            gxr[1] = gp[1 * HID];
            gxr[2] = gp[2 * HID];
            gxr[3] = gp[3 * HID];
            cr = g_c[mm * HID + j0 + jjv];
        }

        float acc[2][4][4];
        #pragma unroll
        for (int mt = 0; mt < 2; mt++)
            #pragma unroll
            for (int nt = 0; nt < 4; nt++)
                #pragma unroll
                for (int r = 0; r < 4; r++) acc[mt][nt][r] = 0.f;

        #pragma unroll
        for (int cc = 0; cc < 4; cc++) {
            stchunk();
            __syncwarp();
            if (cc < 3) ldchunk(cc + 1);

            #pragma unroll
            for (int kk2 = 0; kk2 < 2; kk2++) {      // 2 x k16 per chunk
                const int wb  = kk2 * 8 + (lane & 3);
                const int kgw = (kbase >> 1) + cc * 16 + kk2 * 8 + (lane & 3);
                unsigned a[2][4], b[4][2];
                #pragma unroll
                for (int mt = 0; mt < 2; mt++) {
                    const uint32_t* ap = myAw + (mt * 16 + (lane >> 2)) * ACH_STR + wb;
                    a[mt][0] = ap[0];
                    a[mt][1] = ap[8 * ACH_STR];
                    a[mt][2] = ap[4];
                    a[mt][3] = ap[8 * ACH_STR + 4];
                }
                #pragma unroll
                for (int nt = 0; nt < 4; nt++) {
                    const uint32_t* bp = Bw + (nt * 8 + (lane >> 2)) * BH_STR + kgw;
                    b[nt][0] = bp[0];
                    b[nt][1] = bp[4];
                }
                #pragma unroll
                for (int mt = 0; mt < 2; mt++)
                    #pragma unroll
                    for (int nt = 0; nt < 4; nt++)
                        mma_f16(acc[mt][nt], a[mt], b[nt]);
            }
            __syncwarp();
        }

        // ---- write partials into own buffer ----
        #pragma unroll
        for (int mt = 0; mt < 2; mt++)
            #pragma unroll
            for (int nt = 0; nt < 4; nt++)
                #pragma unroll
                for (int r = 0; r < 4; r++)
                    myP[((mt * 4 + nt) * 4 + r) * 32 + lane] = acc[mt][nt][r];
        __syncthreads();

        // ---- reduce across 8 k-slices + cell update (1 position/thread) ----
        {
            float g[4];
            #pragma unroll
            for (int nt = 0; nt < 4; nt++) {
                float s = 0.f;
                #pragma unroll
                for (int ks = 0; ks < 8; ks++)       // same order as v4 -> bit-identical
                    s += Part[(ks * 2 + mho) * PART_WARP + base_pw[nt]];
                g[nt] = s;
            }
            float gi = g[0] + gxr[0];
            float gf = g[1] + gxr[1];
            float gg = g[2] + gxr[2];
            float go = g[3] + gxr[3];
            float si = 1.f / (1.f + expf(-gi));
            float sf = 1.f / (1.f + expf(-gf));
            float so = 1.f / (1.f + expf(-go));
            float cn = sf * cr + si * tanhf(gg);
            float hn = so * tanhf(cn);
            int cidx = mm * HID + j0 + jjv;
            g_c[cidx]   = cn;
            hhout[cidx] = __float2half(hn);
            hfout[cidx] = hn;
        }
        __syncthreads();

        // ---- grid barrier (R8-proven form) ----
        if (tid == 0) {
            __threadfence();
            atomicAdd(&g_bar, 1u);
            unsigned target = (unsigned)(t + 1) * GRID;
            while (*(volatile unsigned*)&g_bar < target) { }
            __threadfence();
        }
        __syncthreads();
    }
}

// ============================================================================
// ar_step (unchanged): gates = g_b + h @ Wsum^T ; fp32/tf32 path; writes output
// ============================================================================
__global__ __launch_bounds__(256) void ar_step_kernel(int t, float* __restrict__ out_slot) {
    __shared__ float smem[64 * 36 + 32 * 36];
    float (*As)[36] = reinterpret_cast<float(*)[36]>(smem);
    float (*Bs)[36] = reinterpret_cast<float(*)[36]>(smem + 64 * 36);

    const int tid = threadIdx.x, wid = tid >> 5, lane = tid & 31;
    const int wn = wid & 3;
    const int wm = wid >> 2;
    const int j0 = blockIdx.x * 8;

    const float* __restrict__ h_in  = g_h[t & 1];
    float*       __restrict__ h_out = g_h[(t + 1) & 1];
    const float* __restrict__ W     = g_wsum;

    float c[2][4];
    #pragma unroll
    for (int mt = 0; mt < 2; mt++) {
        int jj = 2 * (lane & 3);
        int n  = wn * HID + j0 + jj;
        float b0 = g_b[n], b1 = g_b[n + 1];
        c[mt][0] = b0; c[mt][1] = b1;
        c[mt][2] = b0; c[mt][3] = b1;
    }

    float4 ra[2], rb;
    auto loadG = [&](int kc) {
        const int k0 = kc * 32;
        #pragma unroll
        for (int i = 0; i < 2; i++) {
            int l = tid + i * 256;
            int r = l >> 3, f = l & 7;
            ra[i] = *reinterpret_cast<const float4*>(h_in + (size_t)r * HID + k0 + f * 4);
        }
        {
            int r = tid >> 3, f = tid & 7;
            int gate = r >> 3, jj2 = r & 7;
            rb = *reinterpret_cast<const float4*>(
                W + (size_t)(gate * HID + j0 + jj2) * HID + k0 + f * 4);
        }
    };

    loadG(0);
    for (int kc = 0; kc < 32; kc++) {
        #pragma unroll
        for (int i = 0; i < 2; i++) {
            int l = tid + i * 256;
            int r = l >> 3, f = l & 7;
            float4 va = ra[i];
            va.x = tfr(va.x); va.y = tfr(va.y); va.z = tfr(va.z); va.w = tfr(va.w);
            *reinterpret_cast<float4*>(&As[r][f * 4]) = va;
        }
        {
            int r = tid >> 3, f = tid & 7;
            float4 vb = rb;
            vb.x = tfr(vb.x); vb.y = tfr(vb.y); vb.z = tfr(vb.z); vb.w = tfr(vb.w);
            *reinterpret_cast<float4*>(&Bs[r][f * 4]) = vb;
        }
        __syncthreads();
        if (kc + 1 < 32) loadG(kc + 1);

        #pragma unroll
        for (int kk = 0; kk < 4; kk++) {
            const int k8 = kk * 8;
            unsigned a[2][4], b[2];
            #pragma unroll
            for (int mt = 0; mt < 2; mt++) {
                int r0 = wm * 32 + mt * 16 + (lane >> 2);
                a[mt][0] = __float_as_uint(As[r0][k8 + (lane & 3)]);
                a[mt][1] = __float_as_uint(As[r0 + 8][k8 + (lane & 3)]);
                a[mt][2] = __float_as_uint(As[r0][k8 + (lane & 3) + 4]);
                a[mt][3] = __float_as_uint(As[r0 + 8][k8 + (lane & 3) + 4]);
            }
            {
                int rb2 = wn * 8 + (lane >> 2);
                b[0] = __float_as_uint(Bs[rb2][k8 + (lane & 3)]);
                b[1] = __float_as_uint(Bs[rb2][k8 + (lane & 3) + 4]);
            }
            #pragma unroll
            for (int mt = 0; mt < 2; mt++)
                mma_tf32(c[mt], a[mt], b);
        }
        __syncthreads();
    }

    float* sg = smem;
    #pragma unroll
    for (int mt = 0; mt < 2; mt++) {
        int row = wm * 32 + mt * 16 + (lane >> 2);
        int jj  = 2 * (lane & 3);
        sg[(wn * 64 + row) * 9 + jj]         = c[mt][0];
        sg[(wn * 64 + row) * 9 + jj + 1]     = c[mt][1];
        sg[(wn * 64 + row + 8) * 9 + jj]     = c[mt][2];
        sg[(wn * 64 + row + 8) * 9 + jj + 1] = c[mt][3];
    }
    __syncthreads();

    for (int q = tid; q < BATCH * 8; q += 256) {
        int m = q >> 3, jj = q & 7;
        float gi = sg[(0 * 64 + m) * 9 + jj];
        float gf = sg[(1 * 64 + m) * 9 + jj];
        float gg = sg[(2 * 64 + m) * 9 + jj];
        float go = sg[(3 * 64 + m) * 9 + jj];
        int cidx = m * HID + j0 + jj;
        float cold = g_c[cidx];
        float si = 1.f / (1.f + expf(-gi));
        float sf = 1.f / (1.f + expf(-gf));
        float so = 1.f / (1.f + expf(-go));
        float cn = sf * cold + si * tanhf(gg);
        float hn = so * tanhf(cn);
        g_c[cidx]      = cn;
        h_out[cidx]    = hn;
        out_slot[cidx] = hn;
    }
}

// ============================================================================
// launch
// ============================================================================
extern "C" void kernel_launch(void* const* d_in, const int* in_sizes, int n_in,
                              void* d_out, int out_size) {
    (void)in_sizes; (void)n_in; (void)out_size;
    const float* x    = (const float*)d_in[0];
    const float* hx0  = (const float*)d_in[1];
    const float* cx0  = (const float*)d_in[2];
    const float* W_ih = (const float*)d_in[3];
    const float* W_hh = (const float*)d_in[4];
    const float* b_ih = (const float*)d_in[5];
    const float* b_hh = (const float*)d_in[6];
    float* out = (float*)d_out;

    static bool attr_set = false;
    if (!attr_set) {
        cudaFuncSetAttribute(persist_kernel,
                             cudaFuncAttributeMaxDynamicSharedMemorySize, SM_TOTAL_P);
        cudaFuncSetAttribute(gemmA_kernel,
                             cudaFuncAttributeMaxDynamicSharedMemorySize, GA_SMEM);
        attr_set = true;
    }

    prep_kernel<<<(NG * HID + 255) / 256, 256>>>(W_ih, W_hh, b_ih, b_hh, hx0, cx0);

    dim3 gA(NG / 128, MTOT / 128);
    gemmA_kernel<<<gA, 256, GA_SMEM>>>(x, W_ih);

    persist_kernel<<<GRID, PTHR, SM_TOTAL_P>>>(W_hh);

    for (int t = S_LEN; t < S_LEN + 2; t++)
        ar_step_kernel<<<HID / 8, 256>>>(t, out + (size_t)(t - S_LEN) * BATCH * HID);
}

// round 16
// speedup vs baseline: 1.0187x; 1.0187x over previous
#include <cuda_runtime.h>
#include <cuda_fp16.h>
#include <cstdint>
#include <cstddef>

#define S_LEN 512
#define BATCH 64
#define HID   1024
#define NG    4096            // 4*HID
#define MTOT  (S_LEN*BATCH)   // 32768
#define GRID  128             // persistent CTAs (HID/8)
#define PTHR  256             // persist threads (8 warps; R13-proven)

// persist SMEM (fp16 W + fp16 A chunks + fp32 partials) — R13 layout
#define BH_STR 532                        // W row stride in 32-bit words (512+20; %32==20)
#define ACH_STR 20                        // A chunk row stride in words (16+4; %32==20)
#define ACH_WARP (64 * ACH_STR)           // 1280 words per warp chunk buffer
#define AWF 2304                          // fp32 partials per warp (2048 used + pad)
#define SM_BW_BYTES (32 * BH_STR * 4)     // 68096
#define SM_ACH_OFF  SM_BW_BYTES
#define SM_ACH_BYTES (8 * ACH_WARP * 4)   // 40960
#define SM_PART_OFF (SM_ACH_OFF + SM_ACH_BYTES)   // 109056
#define SM_TOTAL_P  (SM_PART_OFF + 8 * AWF * 4)   // 182784 (~178.5KB)

// gemmA v3: CTA tile 128x128, 4 stages x (As[128][36] + Bs[128][36])
#define GA_STGF ((128 + 128) * 36)
#define GA_SMEM (4 * GA_STGF * 4)

// ---- scratch (device globals; no runtime allocation) ----
__device__ float  g_gx[(size_t)MTOT * NG];   // precomputed x@W_ih^T + b
__device__ float  g_h[2][BATCH * HID];       // fp32 hidden (for ar_step)
__device__ __half g_hh[2][BATCH * HID];      // fp16 hidden (persist datapath)
__device__ float  g_c[BATCH * HID];          // cell state (fp32)
__device__ float  g_b[NG];                   // b_ih + b_hh
__device__ float  g_wsum[(size_t)NG * HID];  // W_ih + W_hh (AR steps)
__device__ unsigned g_arr[GRID];             // per-CTA barrier flags (monotonic)

// ---- helpers ----
__device__ __forceinline__ float tfr(float f) {
    unsigned u;
    asm("cvt.rna.tf32.f32 %0, %1;" : "=r"(u) : "f"(f));
    return __uint_as_float(u);
}

__device__ __forceinline__ void mma_tf32(float c[4], const unsigned a[4], const unsigned b[2]) {
    asm volatile(
        "mma.sync.aligned.m16n8k8.row.col.f32.tf32.tf32.f32 "
        "{%0,%1,%2,%3}, {%4,%5,%6,%7}, {%8,%9}, {%0,%1,%2,%3};\n"
        : "+f"(c[0]), "+f"(c[1]), "+f"(c[2]), "+f"(c[3])
        : "r"(a[0]), "r"(a[1]), "r"(a[2]), "r"(a[3]), "r"(b[0]), "r"(b[1]));
}

__device__ __forceinline__ void mma_f16(float c[4], const unsigned a[4], const unsigned b[2]) {
    asm volatile(
        "mma.sync.aligned.m16n8k16.row.col.f32.f16.f16.f32 "
        "{%0,%1,%2,%3}, {%4,%5,%6,%7}, {%8,%9}, {%0,%1,%2,%3};\n"
        : "+f"(c[0]), "+f"(c[1]), "+f"(c[2]), "+f"(c[3])
        : "r"(a[0]), "r"(a[1]), "r"(a[2]), "r"(a[3]), "r"(b[0]), "r"(b[1]));
}

#define CP_ASYNC16(dst_u32, src) \
    asm volatile("cp.async.cg.shared.global [%0], [%1], 16;\n" :: "r"(dst_u32), "l"(src))
#define CP_COMMIT() asm volatile("cp.async.commit_group;\n" ::: "memory")
#define CP_WAIT2()  asm volatile("cp.async.wait_group 2;\n" ::: "memory")

// ============================================================================
// prep: biases, Wsum, h0 (fp32 + fp16), c0, barrier flags = 0
// ============================================================================
__global__ void prep_kernel(const float* __restrict__ W_ih, const float* __restrict__ W_hh,
                            const float* __restrict__ b_ih, const float* __restrict__ b_hh,
                            const float* __restrict__ hx0,  const float* __restrict__ cx0) {
    int idx = blockIdx.x * blockDim.x + threadIdx.x;
    if (idx < GRID) g_arr[idx] = 0;
    if (idx < NG * HID) g_wsum[idx] = W_ih[idx] + W_hh[idx];
    if (idx < NG)       g_b[idx]    = b_ih[idx] + b_hh[idx];
    if (idx < BATCH * HID) {
        g_h[0][idx]  = hx0[idx];
        g_hh[0][idx] = __float2half(hx0[idx]);
        g_c[idx]     = cx0[idx];
    }
}

// ============================================================================
// gemmA v3 (unchanged, R11-proven): CTA tile 128x128, 4-stage cp.async, tf32.
// ============================================================================
__global__ __launch_bounds__(256) void gemmA_kernel(const float* __restrict__ X,
                                                    const float* __restrict__ W) {
    extern __shared__ float gsm[];

    const int tid  = threadIdx.x;
    const int wid  = tid >> 5, lane = tid & 31;
    const int wm   = wid >> 2;
    const int wn   = wid & 3;
    const int m0   = blockIdx.y * 128;
    const int n0   = blockIdx.x * 128;

    const float* Ag = X + (size_t)m0 * HID;
    const float* Bg = W + (size_t)n0 * HID;

    int ar_[4], af_[4];
    #pragma unroll
    for (int i = 0; i < 4; i++) { int l = tid + i * 256; ar_[i] = l >> 3; af_[i] = l & 7; }

    auto issue = [&](int kc) {
        int s = kc & 3;
        float* as = gsm + s * GA_STGF;
        float* bs = as + 128 * 36;
        const int k0 = kc * 32;
        #pragma unroll
        for (int i = 0; i < 4; i++) {
            unsigned dst = (unsigned)__cvta_generic_to_shared(&as[ar_[i] * 36 + af_[i] * 4]);
            CP_ASYNC16(dst, Ag + (size_t)ar_[i] * HID + k0 + af_[i] * 4);
        }
        #pragma unroll
        for (int i = 0; i < 4; i++) {
            unsigned dst = (unsigned)__cvta_generic_to_shared(&bs[ar_[i] * 36 + af_[i] * 4]);
            CP_ASYNC16(dst, Bg + (size_t)ar_[i] * HID + k0 + af_[i] * 4);
        }
        CP_COMMIT();
    };

    float c[4][4][4];
    #pragma unroll
    for (int mt = 0; mt < 4; mt++)
        #pragma unroll
        for (int nt = 0; nt < 4; nt++)
            #pragma unroll
            for (int r = 0; r < 4; r++) c[mt][nt][r] = 0.f;

    issue(0); issue(1); issue(2);

    for (int kc = 0; kc < 32; kc++) {
        CP_WAIT2();
        __syncthreads();
        if (kc + 3 < 32) issue(kc + 3);
        else CP_COMMIT();

        const float* as = gsm + (kc & 3) * GA_STGF;
        const float* bs = as + 128 * 36;

        #pragma unroll
        for (int kk = 0; kk < 4; kk++) {
            const int k8 = kk * 8;
            unsigned a[4][4], b[4][2];
            #pragma unroll
            for (int mt = 0; mt < 4; mt++) {
                int r0 = wm * 64 + mt * 16 + (lane >> 2);
                a[mt][0] = __float_as_uint(tfr(as[r0 * 36 + k8 + (lane & 3)]));
                a[mt][1] = __float_as_uint(tfr(as[(r0 + 8) * 36 + k8 + (lane & 3)]));
                a[mt][2] = __float_as_uint(tfr(as[r0 * 36 + k8 + (lane & 3) + 4]));
                a[mt][3] = __float_as_uint(tfr(as[(r0 + 8) * 36 + k8 + (lane & 3) + 4]));
            }
            #pragma unroll
            for (int nt = 0; nt < 4; nt++) {
                int rn = wn * 32 + nt * 8 + (lane >> 2);
                b[nt][0] = __float_as_uint(tfr(bs[rn * 36 + k8 + (lane & 3)]));
                b[nt][1] = __float_as_uint(tfr(bs[rn * 36 + k8 + (lane & 3) + 4]));
            }
            #pragma unroll
            for (int mt = 0; mt < 4; mt++)
                #pragma unroll
                for (int nt = 0; nt < 4; nt++)
                    mma_tf32(c[mt][nt], a[mt], b[nt]);
        }
    }

    #pragma unroll
    for (int mt = 0; mt < 4; mt++) {
        #pragma unroll
        for (int nt = 0; nt < 4; nt++) {
            int row = m0 + wm * 64 + mt * 16 + (lane >> 2);
            int col = n0 + wn * 32 + nt * 8 + 2 * (lane & 3);
            float b0 = g_b[col], b1 = g_b[col + 1];
            g_gx[(size_t)row * NG + col]           = c[mt][nt][0] + b0;
            g_gx[(size_t)row * NG + col + 1]       = c[mt][nt][1] + b1;
            g_gx[(size_t)(row + 8) * NG + col]     = c[mt][nt][2] + b0;
            g_gx[(size_t)(row + 8) * NG + col + 1] = c[mt][nt][3] + b1;
        }
    }
}

// ============================================================================
// persist v6 = R13-proven body (fp16, 8 warps, K-split) with flag-array barrier.
// ============================================================================
__global__ __launch_bounds__(PTHR) void persist_kernel(const float* __restrict__ Whh) {
    extern __shared__ float sm[];
    uint32_t* Bw   = reinterpret_cast<uint32_t*>(sm);                 // W fp16: [32][BH_STR] words
    uint32_t* Aw   = reinterpret_cast<uint32_t*>(
                         reinterpret_cast<char*>(sm) + SM_ACH_OFF);   // 8 x [64][ACH_STR] words
    float*    Part = reinterpret_cast<float*>(
                         reinterpret_cast<char*>(sm) + SM_PART_OFF);  // 8 x AWF fp32

    const int tid = threadIdx.x, wid = tid >> 5, lane = tid & 31;
    const int j0 = blockIdx.x * 8;
    uint32_t* myAw = Aw + wid * ACH_WARP;
    float*    myP  = Part + wid * AWF;
    const int kbase = wid * 128;       // this warp's K-slice

    // ---- prologue: W slice -> fp16 SMEM, rows rn = gate*8+jj, k word-packed ----
    for (int i = tid; i < 32 * 512; i += PTHR) {     // 16384 words
        int rn = i >> 9, w = i & 511;
        int gate = rn >> 3, jj = rn & 7;
        const float* wp = Whh + (size_t)(gate * HID + j0 + jj) * HID + w * 2;
        __half2 hv = __floats2half2_rn(wp[0], wp[1]);
        Bw[rn * BH_STR + w] = *reinterpret_cast<uint32_t*>(&hv);
    }
    __syncthreads();

    // reduce-phase position mapping (2 positions per thread) — R13 mapping
    int   mm[2], jjv[2], base_pw[2][4];
    #pragma unroll
    for (int pi = 0; pi < 2; pi++) {
        int p  = tid + pi * 256;
        int mt = p >> 7, r = (p >> 5) & 3, ln = p & 31;
        mm[pi]  = mt * 16 + (ln >> 2) + 8 * (r >> 1);
        jjv[pi] = 2 * (ln & 3) + (r & 1);
        #pragma unroll
        for (int nt = 0; nt < 4; nt++)
            base_pw[pi][nt] = ((mt * 4 + nt) * 4 + r) * 32 + ln;
    }

    for (int t = 0; t < S_LEN; t++) {
        const __half* __restrict__ hin   = g_hh[t & 1];
        __half*       __restrict__ hhout = g_hh[(t + 1) & 1];
        float*        __restrict__ hfout = g_h[(t + 1) & 1];
        const float*  __restrict__ gx_t  = g_gx + (size_t)t * BATCH * NG;

        // prefetch gx + c for the reduce phase (hidden under GEMM)
        float gxr[2][4], cr[2];
        #pragma unroll
        for (int pi = 0; pi < 2; pi++) {
            const float* gp = gx_t + (size_t)mm[pi] * NG + j0 + jjv[pi];
            gxr[pi][0] = gp[0 * HID];
            gxr[pi][1] = gp[1 * HID];
            gxr[pi][2] = gp[2 * HID];
            gxr[pi][3] = gp[3 * HID];
            cr[pi] = g_c[mm[pi] * HID + j0 + jjv[pi]];
        }

        // ---- per-warp GEMM over own K-slice; 4 chunks of 32 k; no block syncs ----
        uint4 pf[8];
        auto ldchunk = [&](int cc) {
            #pragma unroll
            for (int i = 0; i < 8; i++) {
                int u = lane + 32 * i;
                int r = u >> 2, w4 = u & 3;          // 64 rows x 4 uint4 (32 halves)
                pf[i] = __ldcg(reinterpret_cast<const uint4*>(
                    hin + (size_t)r * HID + kbase + cc * 32 + w4 * 8));
            }
        };
        auto stchunk = [&]() {
            #pragma unroll
            for (int i = 0; i < 8; i++) {
                int u = lane + 32 * i;
                int r = u >> 2, w4 = u & 3;
                *reinterpret_cast<uint4*>(myAw + r * ACH_STR + w4 * 4) = pf[i];
            }
        };

        float acc[4][4][4];
        #pragma unroll
        for (int mt = 0; mt < 4; mt++)
            #pragma unroll
            for (int nt = 0; nt < 4; nt++)
                #pragma unroll
                for (int r = 0; r < 4; r++) acc[mt][nt][r] = 0.f;

        ldchunk(0);
        #pragma unroll
        for (int cc = 0; cc < 4; cc++) {
            stchunk();
            __syncwarp();
            if (cc < 3) ldchunk(cc + 1);

            #pragma unroll
            for (int kk2 = 0; kk2 < 2; kk2++) {      // 2 x k16 per chunk
                const int wb  = kk2 * 8 + (lane & 3);
                const int kgw = (kbase >> 1) + cc * 16 + kk2 * 8 + (lane & 3);
                unsigned a[4][4], b[4][2];
                #pragma unroll
                for (int mt = 0; mt < 4; mt++) {
                    const uint32_t* ap = myAw + (mt * 16 + (lane >> 2)) * ACH_STR + wb;
                    a[mt][0] = ap[0];
                    a[mt][1] = ap[8 * ACH_STR];
                    a[mt][2] = ap[4];
                    a[mt][3] = ap[8 * ACH_STR + 4];
                }
                #pragma unroll
                for (int nt = 0; nt < 4; nt++) {
                    const uint32_t* bp = Bw + (nt * 8 + (lane >> 2)) * BH_STR + kgw;
                    b[nt][0] = bp[0];
                    b[nt][1] = bp[4];
                }
                #pragma unroll
                for (int mt = 0; mt < 4; mt++)
                    #pragma unroll
                    for (int nt = 0; nt < 4; nt++)
                        mma_f16(acc[mt][nt], a[mt], b[nt]);
            }
            __syncwarp();
        }

        // ---- write partials into own buffer ----
        #pragma unroll
        for (int mt = 0; mt < 4; mt++)
            #pragma unroll
            for (int nt = 0; nt < 4; nt++)
                #pragma unroll
                for (int r = 0; r < 4; r++)
                    myP[((mt * 4 + nt) * 4 + r) * 32 + lane] = acc[mt][nt][r];
        __syncthreads();

        // ---- reduce across 8 k-slices + cell update (512 positions) ----
        #pragma unroll
        for (int pi = 0; pi < 2; pi++) {
            float g[4];
            #pragma unroll
            for (int nt = 0; nt < 4; nt++) {
                float s = 0.f;
                #pragma unroll
                for (int w = 0; w < 8; w++)
                    s += Part[w * AWF + base_pw[pi][nt]];
                g[nt] = s;
            }
            float gi = g[0] + gxr[pi][0];
            float gf = g[1] + gxr[pi][1];
            float gg = g[2] + gxr[pi][2];
            float go = g[3] + gxr[pi][3];
            float si = 1.f / (1.f + expf(-gi));
            float sf = 1.f / (1.f + expf(-gf));
            float so = 1.f / (1.f + expf(-go));
            float cn = sf * cr[pi] + si * tanhf(gg);
            float hn = so * tanhf(cn);
            int cidx = mm[pi] * HID + j0 + jjv[pi];
            g_c[cidx]   = cn;
            hhout[cidx] = __float2half(hn);
            hfout[cidx] = hn;
        }
        __syncthreads();

        // ---- grid barrier: per-CTA flags (no single-address contention) ----
        if (tid == 0) {
            __threadfence();                              // order h stores before flag
            atomicExch(&g_arr[blockIdx.x], (unsigned)(t + 1));
        }
        if (tid < GRID) {
            while (*(volatile unsigned*)&g_arr[tid] < (unsigned)(t + 1)) { }
        }
        if (tid == 0) __threadfence();
        __syncthreads();
    }
}

// ============================================================================
// ar_step (unchanged): gates = g_b + h @ Wsum^T ; fp32/tf32 path; writes output
// ============================================================================
__global__ __launch_bounds__(256) void ar_step_kernel(int t, float* __restrict__ out_slot) {
    __shared__ float smem[64 * 36 + 32 * 36];
    float (*As)[36] = reinterpret_cast<float(*)[36]>(smem);
    float (*Bs)[36] = reinterpret_cast<float(*)[36]>(smem + 64 * 36);

    const int tid = threadIdx.x, wid = tid >> 5, lane = tid & 31;
    const int wn = wid & 3;
    const int wm = wid >> 2;
    const int j0 = blockIdx.x * 8;

    const float* __restrict__ h_in  = g_h[t & 1];
    float*       __restrict__ h_out = g_h[(t + 1) & 1];
    const float* __restrict__ W     = g_wsum;

    float c[2][4];
    #pragma unroll
    for (int mt = 0; mt < 2; mt++) {
        int jj = 2 * (lane & 3);
        int n  = wn * HID + j0 + jj;
        float b0 = g_b[n], b1 = g_b[n + 1];
        c[mt][0] = b0; c[mt][1] = b1;
        c[mt][2] = b0; c[mt][3] = b1;
    }

    float4 ra[2], rb;
    auto loadG = [&](int kc) {
        const int k0 = kc * 32;
        #pragma unroll
        for (int i = 0; i < 2; i++) {
            int l = tid + i * 256;
            int r = l >> 3, f = l & 7;
            ra[i] = *reinterpret_cast<const float4*>(h_in + (size_t)r * HID + k0 + f * 4);
        }
        {
            int r = tid >> 3, f = tid & 7;
            int gate = r >> 3, jj2 = r & 7;
            rb = *reinterpret_cast<const float4*>(
                W + (size_t)(gate * HID + j0 + jj2) * HID + k0 + f * 4);
        }
    };

    loadG(0);
    for (int kc = 0; kc < 32; kc++) {
        #pragma unroll
        for (int i = 0; i < 2; i++) {
            int l = tid + i * 256;
            int r = l >> 3, f = l & 7;
            float4 va = ra[i];
            va.x = tfr(va.x); va.y = tfr(va.y); va.z = tfr(va.z); va.w = tfr(va.w);
            *reinterpret_cast<float4*>(&As[r][f * 4]) = va;
        }
        {
            int r = tid >> 3, f = tid & 7;
            float4 vb = rb;
            vb.x = tfr(vb.x); vb.y = tfr(vb.y); vb.z = tfr(vb.z); vb.w = tfr(vb.w);
            *reinterpret_cast<float4*>(&Bs[r][f * 4]) = vb;
        }
        __syncthreads();
        if (kc + 1 < 32) loadG(kc + 1);

        #pragma unroll
        for (int kk = 0; kk < 4; kk++) {
            const int k8 = kk * 8;
            unsigned a[2][4], b[2];
            #pragma unroll
            for (int mt = 0; mt < 2; mt++) {
                int r0 = wm * 32 + mt * 16 + (lane >> 2);
                a[mt][0] = __float_as_uint(As[r0][k8 + (lane & 3)]);
                a[mt][1] = __float_as_uint(As[r0 + 8][k8 + (lane & 3)]);
                a[mt][2] = __float_as_uint(As[r0][k8 + (lane & 3) + 4]);
                a[mt][3] = __float_as_uint(As[r0 + 8][k8 + (lane & 3) + 4]);
            }
            {
                int rb2 = wn * 8 + (lane >> 2);
                b[0] = __float_as_uint(Bs[rb2][k8 + (lane & 3)]);
                b[1] = __float_as_uint(Bs[rb2][k8 + (lane & 3) + 4]);
            }
            #pragma unroll
            for (int mt = 0; mt < 2; mt++)
                mma_tf32(c[mt], a[mt], b);
        }
        __syncthreads();
    }

    float* sg = smem;
    #pragma unroll
    for (int mt = 0; mt < 2; mt++) {
        int row = wm * 32 + mt * 16 + (lane >> 2);
        int jj  = 2 * (lane & 3);
        sg[(wn * 64 + row) * 9 + jj]         = c[mt][0];
        sg[(wn * 64 + row) * 9 + jj + 1]     = c[mt][1];
        sg[(wn * 64 + row + 8) * 9 + jj]     = c[mt][2];
        sg[(wn * 64 + row + 8) * 9 + jj + 1] = c[mt][3];
    }
    __syncthreads();

    for (int q = tid; q < BATCH * 8; q += 256) {
        int m = q >> 3, jj = q & 7;
        float gi = sg[(0 * 64 + m) * 9 + jj];
        float gf = sg[(1 * 64 + m) * 9 + jj];
        float gg = sg[(2 * 64 + m) * 9 + jj];
        float go = sg[(3 * 64 + m) * 9 + jj];
        int cidx = m * HID + j0 + jj;
        float cold = g_c[cidx];
        float si = 1.f / (1.f + expf(-gi));
        float sf = 1.f / (1.f + expf(-gf));
        float so = 1.f / (1.f + expf(-go));
        float cn = sf * cold + si * tanhf(gg);
        float hn = so * tanhf(cn);
        g_c[cidx]      = cn;
        h_out[cidx]    = hn;
        out_slot[cidx] = hn;
    }
}

// ============================================================================
// launch
// ============================================================================
extern "C" void kernel_launch(void* const* d_in, const int* in_sizes, int n_in,
                              void* d_out, int out_size) {
    (void)in_sizes; (void)n_in; (void)out_size;
    const float* x    = (const float*)d_in[0];
    const float* hx0  = (const float*)d_in[1];
    const float* cx0  = (const float*)d_in[2];
    const float* W_ih = (const float*)d_in[3];
    const float* W_hh = (const float*)d_in[4];
    const float* b_ih = (const float*)d_in[5];
    const float* b_hh = (const float*)d_in[6];
    float* out = (float*)d_out;

    static bool attr_set = false;
    if (!attr_set) {
        cudaFuncSetAttribute(persist_kernel,
                             cudaFuncAttributeMaxDynamicSharedMemorySize, SM_TOTAL_P);
        cudaFuncSetAttribute(gemmA_kernel,
                             cudaFuncAttributeMaxDynamicSharedMemorySize, GA_SMEM);
        attr_set = true;
    }

    prep_kernel<<<(NG * HID + 255) / 256, 256>>>(W_ih, W_hh, b_ih, b_hh, hx0, cx0);

    dim3 gA(NG / 128, MTOT / 128);
    gemmA_kernel<<<gA, 256, GA_SMEM>>>(x, W_ih);

    persist_kernel<<<GRID, PTHR, SM_TOTAL_P>>>(W_hh);

    for (int t = S_LEN; t < S_LEN + 2; t++)
        ar_step_kernel<<<HID / 8, 256>>>(t, out + (size_t)(t - S_LEN) * BATCH * HID);
}

// round 17
// speedup vs baseline: 1.2330x; 1.2104x over previous
#include <cuda_runtime.h>
#include <cuda_fp16.h>
#include <cstdint>
#include <cstddef>

#define S_LEN 512
#define BATCH 64
#define HID   1024
#define NG    4096            // 4*HID
#define MTOT  (S_LEN*BATCH)   // 32768
#define GRID  128             // persistent CTAs (HID/8)
#define PTHR  256             // persist threads (8 warps; R13-proven)

// persist SMEM (fp16 W + fp16 A chunks + fp32 partials) — R13 layout
#define BH_STR 532                        // W row stride in 32-bit words (512+20; %32==20)
#define ACH_STR 20                        // A chunk row stride in words (16+4; %32==20)
#define ACH_WARP (64 * ACH_STR)           // 1280 words per warp chunk buffer
#define AWF 2304                          // fp32 partials per warp (2048 used + pad)
#define SM_BW_BYTES (32 * BH_STR * 4)     // 68096
#define SM_ACH_OFF  SM_BW_BYTES
#define SM_ACH_BYTES (8 * ACH_WARP * 4)   // 40960
#define SM_PART_OFF (SM_ACH_OFF + SM_ACH_BYTES)   // 109056
#define SM_TOTAL_P  (SM_PART_OFF + 8 * AWF * 4)   // 182784 (~178.5KB)

// gemmA v4 (fp16): CTA tile 128x128, K-chunk 32 halves, 4 stages.
// Stage = A[128][20w] + B[128][20w] = 5120 words.
#define GAH_STG_W (256 * ACH_STR)         // 5120 words per stage
#define GAH_SMEM  (4 * GAH_STG_W * 4)     // 81920 bytes

// ---- scratch (device globals; no runtime allocation) ----
__device__ float  g_gx[(size_t)MTOT * NG];   // precomputed x@W_ih^T + b
__device__ float  g_h[2][BATCH * HID];       // fp32 hidden (for ar_step)
__device__ __half g_hh[2][BATCH * HID];      // fp16 hidden (persist datapath)
__device__ __half g_xh[(size_t)MTOT * HID];  // fp16 copy of x (gemmA datapath)
__device__ __half g_wihh[(size_t)NG * HID];  // fp16 copy of W_ih
__device__ float  g_c[BATCH * HID];          // cell state (fp32)
__device__ float  g_b[NG];                   // b_ih + b_hh
__device__ float  g_wsum[(size_t)NG * HID];  // W_ih + W_hh (AR steps)
__device__ unsigned g_bar;                   // grid barrier counter (monotonic)

// ---- helpers ----
__device__ __forceinline__ float tfr(float f) {
    unsigned u;
    asm("cvt.rna.tf32.f32 %0, %1;" : "=r"(u) : "f"(f));
    return __uint_as_float(u);
}

__device__ __forceinline__ void mma_tf32(float c[4], const unsigned a[4], const unsigned b[2]) {
    asm volatile(
        "mma.sync.aligned.m16n8k8.row.col.f32.tf32.tf32.f32 "
        "{%0,%1,%2,%3}, {%4,%5,%6,%7}, {%8,%9}, {%0,%1,%2,%3};\n"
        : "+f"(c[0]), "+f"(c[1]), "+f"(c[2]), "+f"(c[3])
        : "r"(a[0]), "r"(a[1]), "r"(a[2]), "r"(a[3]), "r"(b[0]), "r"(b[1]));
}

__device__ __forceinline__ void mma_f16(float c[4], const unsigned a[4], const unsigned b[2]) {
    asm volatile(
        "mma.sync.aligned.m16n8k16.row.col.f32.f16.f16.f32 "
        "{%0,%1,%2,%3}, {%4,%5,%6,%7}, {%8,%9}, {%0,%1,%2,%3};\n"
        : "+f"(c[0]), "+f"(c[1]), "+f"(c[2]), "+f"(c[3])
        : "r"(a[0]), "r"(a[1]), "r"(a[2]), "r"(a[3]), "r"(b[0]), "r"(b[1]));
}

#define CP_ASYNC16(dst_u32, src) \
    asm volatile("cp.async.cg.shared.global [%0], [%1], 16;\n" :: "r"(dst_u32), "l"(src))
#define CP_COMMIT() asm volatile("cp.async.commit_group;\n" ::: "memory")
#define CP_WAIT2()  asm volatile("cp.async.wait_group 2;\n" ::: "memory")

// ============================================================================
// prep: biases, Wsum, h0 (fp32+fp16), c0, fp16 copies of x and W_ih, bar=0
// ============================================================================
__global__ void prep_kernel(const float* __restrict__ W_ih, const float* __restrict__ W_hh,
                            const float* __restrict__ b_ih, const float* __restrict__ b_hh,
                            const float* __restrict__ hx0,  const float* __restrict__ cx0,
                            const float* __restrict__ x) {
    int idx = blockIdx.x * blockDim.x + threadIdx.x;
    if (idx == 0) g_bar = 0;
    if (idx < NG * HID) {
        float wv = W_ih[idx];
        g_wsum[idx] = wv + W_hh[idx];
        g_wihh[idx] = __float2half(wv);
    }
    if (idx < NG) g_b[idx] = b_ih[idx] + b_hh[idx];
    if (idx < BATCH * HID) {
        g_h[0][idx]  = hx0[idx];
        g_hh[0][idx] = __float2half(hx0[idx]);
        g_c[idx]     = cx0[idx];
    }
    // x -> fp16 (33.5M elements over 4.19M threads: 8 strided passes)
    for (size_t k = idx; k < (size_t)MTOT * HID; k += (size_t)NG * HID)
        g_xh[k] = __float2half(x[k]);
}

// ============================================================================
// gemmA v4 (fp16): g_gx = X @ W_ih^T + b. CTA tile 128x128, 8 warps
// (wm 0..1 x wn 0..3), warp tile 64x32, m16n8k16, 4-stage cp.async.
// Fragment indexing identical to the proven persist fp16 pattern.
// ============================================================================
__global__ __launch_bounds__(256) void gemmA_kernel() {
    extern __shared__ uint32_t gsw[];

    const int tid  = threadIdx.x;
    const int wid  = tid >> 5, lane = tid & 31;
    const int wm   = wid >> 2;      // 0..1 (64-row block)
    const int wn   = wid & 3;       // 0..3 (32-col block)
    const int m0   = blockIdx.y * 128;
    const int n0   = blockIdx.x * 128;

    const __half* Ag = g_xh   + (size_t)m0 * HID;
    const __half* Bg = g_wihh + (size_t)n0 * HID;

    auto issue = [&](int kc) {
        uint32_t* st = gsw + (kc & 3) * GAH_STG_W;
        const int k0 = kc * 32;                      // halves
        #pragma unroll
        for (int j = 0; j < 2; j++) {
            int u = tid * 2 + j;                     // 0..511
            int row = u >> 2, quad = u & 3;
            unsigned da = (unsigned)__cvta_generic_to_shared(st + row * ACH_STR + quad * 4);
            CP_ASYNC16(da, Ag + (size_t)row * HID + k0 + quad * 8);
            unsigned db = (unsigned)__cvta_generic_to_shared(
                st + 128 * ACH_STR + row * ACH_STR + quad * 4);
            CP_ASYNC16(db, Bg + (size_t)row * HID + k0 + quad * 8);
        }
        CP_COMMIT();
    };

    float c[4][4][4];
    #pragma unroll
    for (int mt = 0; mt < 4; mt++)
        #pragma unroll
        for (int nt = 0; nt < 4; nt++)
            #pragma unroll
            for (int r = 0; r < 4; r++) c[mt][nt][r] = 0.f;

    issue(0); issue(1); issue(2);

    for (int kc = 0; kc < 32; kc++) {
        CP_WAIT2();
        __syncthreads();
        if (kc + 3 < 32) issue(kc + 3);
        else CP_COMMIT();

        const uint32_t* as = gsw + (kc & 3) * GAH_STG_W;
        const uint32_t* bs = as + 128 * ACH_STR;

        #pragma unroll
        for (int kk2 = 0; kk2 < 2; kk2++) {          // 2 x k16 per 32-half chunk
            const int wb = kk2 * 8 + (lane & 3);
            unsigned a[4][4], b[4][2];
            #pragma unroll
            for (int mt = 0; mt < 4; mt++) {
                const uint32_t* ap = as + (wm * 64 + mt * 16 + (lane >> 2)) * ACH_STR + wb;
                a[mt][0] = ap[0];
                a[mt][1] = ap[8 * ACH_STR];
                a[mt][2] = ap[4];
                a[mt][3] = ap[8 * ACH_STR + 4];
            }
            #pragma unroll
            for (int nt = 0; nt < 4; nt++) {
                const uint32_t* bp = bs + (wn * 32 + nt * 8 + (lane >> 2)) * ACH_STR + wb;
                b[nt][0] = bp[0];
                b[nt][1] = bp[4];
            }
            #pragma unroll
            for (int mt = 0; mt < 4; mt++)
                #pragma unroll
                for (int nt = 0; nt < 4; nt++)
                    mma_f16(c[mt][nt], a[mt], b[nt]);
        }
    }

    #pragma unroll
    for (int mt = 0; mt < 4; mt++) {
        #pragma unroll
        for (int nt = 0; nt < 4; nt++) {
            int row = m0 + wm * 64 + mt * 16 + (lane >> 2);
            int col = n0 + wn * 32 + nt * 8 + 2 * (lane & 3);
            float b0 = g_b[col], b1 = g_b[col + 1];
            g_gx[(size_t)row * NG + col]           = c[mt][nt][0] + b0;
            g_gx[(size_t)row * NG + col + 1]       = c[mt][nt][1] + b1;
            g_gx[(size_t)(row + 8) * NG + col]     = c[mt][nt][2] + b0;
            g_gx[(size_t)(row + 8) * NG + col + 1] = c[mt][nt][3] + b1;
        }
    }
}

// ============================================================================
// persist = R13-proven body (fp16, 8 warps, K-split, single-counter barrier).
// Only change: fp32 h written solely at the final step (ar_step handoff).
// ============================================================================
__global__ __launch_bounds__(PTHR) void persist_kernel(const float* __restrict__ Whh) {
    extern __shared__ float sm[];
    uint32_t* Bw   = reinterpret_cast<uint32_t*>(sm);                 // W fp16: [32][BH_STR] words
    uint32_t* Aw   = reinterpret_cast<uint32_t*>(
                         reinterpret_cast<char*>(sm) + SM_ACH_OFF);   // 8 x [64][ACH_STR] words
    float*    Part = reinterpret_cast<float*>(
                         reinterpret_cast<char*>(sm) + SM_PART_OFF);  // 8 x AWF fp32

    const int tid = threadIdx.x, wid = tid >> 5, lane = tid & 31;
    const int j0 = blockIdx.x * 8;
    uint32_t* myAw = Aw + wid * ACH_WARP;
    float*    myP  = Part + wid * AWF;
    const int kbase = wid * 128;

    // ---- prologue: W slice -> fp16 SMEM ----
    for (int i = tid; i < 32 * 512; i += PTHR) {
        int rn = i >> 9, w = i & 511;
        int gate = rn >> 3, jj = rn & 7;
        const float* wp = Whh + (size_t)(gate * HID + j0 + jj) * HID + w * 2;
        __half2 hv = __floats2half2_rn(wp[0], wp[1]);
        Bw[rn * BH_STR + w] = *reinterpret_cast<uint32_t*>(&hv);
    }
    __syncthreads();

    // reduce-phase position mapping (2 positions per thread)
    int   mm[2], jjv[2], base_pw[2][4];
    #pragma unroll
    for (int pi = 0; pi < 2; pi++) {
        int p  = tid + pi * 256;
        int mt = p >> 7, r = (p >> 5) & 3, ln = p & 31;
        mm[pi]  = mt * 16 + (ln >> 2) + 8 * (r >> 1);
        jjv[pi] = 2 * (ln & 3) + (r & 1);
        #pragma unroll
        for (int nt = 0; nt < 4; nt++)
            base_pw[pi][nt] = ((mt * 4 + nt) * 4 + r) * 32 + ln;
    }

    for (int t = 0; t < S_LEN; t++) {
        const __half* __restrict__ hin   = g_hh[t & 1];
        __half*       __restrict__ hhout = g_hh[(t + 1) & 1];
        float*        __restrict__ hfout = g_h[(t + 1) & 1];
        const float*  __restrict__ gx_t  = g_gx + (size_t)t * BATCH * NG;

        // prefetch gx + c for the reduce phase (hidden under GEMM)
        float gxr[2][4], cr[2];
        #pragma unroll
        for (int pi = 0; pi < 2; pi++) {
            const float* gp = gx_t + (size_t)mm[pi] * NG + j0 + jjv[pi];
            gxr[pi][0] = gp[0 * HID];
            gxr[pi][1] = gp[1 * HID];
            gxr[pi][2] = gp[2 * HID];
            gxr[pi][3] = gp[3 * HID];
            cr[pi] = g_c[mm[pi] * HID + j0 + jjv[pi]];
        }

        // ---- per-warp GEMM over own K-slice; 4 chunks of 32 k; no block syncs ----
        uint4 pf[8];
        auto ldchunk = [&](int cc) {
            #pragma unroll
            for (int i = 0; i < 8; i++) {
                int u = lane + 32 * i;
                int r = u >> 2, w4 = u & 3;
                pf[i] = __ldcg(reinterpret_cast<const uint4*>(
                    hin + (size_t)r * HID + kbase + cc * 32 + w4 * 8));
            }
        };
        auto stchunk = [&]() {
            #pragma unroll
            for (int i = 0; i < 8; i++) {
                int u = lane + 32 * i;
                int r = u >> 2, w4 = u & 3;
                *reinterpret_cast<uint4*>(myAw + r * ACH_STR + w4 * 4) = pf[i];
            }
        };

        float acc[4][4][4];
        #pragma unroll
        for (int mt = 0; mt < 4; mt++)
            #pragma unroll
            for (int nt = 0; nt < 4; nt++)
                #pragma unroll
                for (int r = 0; r < 4; r++) acc[mt][nt][r] = 0.f;

        ldchunk(0);
        #pragma unroll
        for (int cc = 0; cc < 4; cc++) {
            stchunk();
            __syncwarp();
            if (cc < 3) ldchunk(cc + 1);

            #pragma unroll
            for (int kk2 = 0; kk2 < 2; kk2++) {
                const int wb  = kk2 * 8 + (lane & 3);
                const int kgw = (kbase >> 1) + cc * 16 + kk2 * 8 + (lane & 3);
                unsigned a[4][4], b[4][2];
                #pragma unroll
                for (int mt = 0; mt < 4; mt++) {
                    const uint32_t* ap = myAw + (mt * 16 + (lane >> 2)) * ACH_STR + wb;
                    a[mt][0] = ap[0];
                    a[mt][1] = ap[8 * ACH_STR];
                    a[mt][2] = ap[4];
                    a[mt][3] = ap[8 * ACH_STR + 4];
                }
                #pragma unroll
                for (int nt = 0; nt < 4; nt++) {
                    const uint32_t* bp = Bw + (nt * 8 + (lane >> 2)) * BH_STR + kgw;
                    b[nt][0] = bp[0];
                    b[nt][1] = bp[4];
                }
                #pragma unroll
                for (int mt = 0; mt < 4; mt++)
                    #pragma unroll
                    for (int nt = 0; nt < 4; nt++)
                        mma_f16(acc[mt][nt], a[mt], b[nt]);
            }
            __syncwarp();
        }

        // ---- write partials into own buffer ----
        #pragma unroll
        for (int mt = 0; mt < 4; mt++)
            #pragma unroll
            for (int nt = 0; nt < 4; nt++)
                #pragma unroll
                for (int r = 0; r < 4; r++)
                    myP[((mt * 4 + nt) * 4 + r) * 32 + lane] = acc[mt][nt][r];
        __syncthreads();

        // ---- reduce across 8 k-slices + cell update (512 positions) ----
        #pragma unroll
        for (int pi = 0; pi < 2; pi++) {
            float g[4];
            #pragma unroll
            for (int nt = 0; nt < 4; nt++) {
                float s = 0.f;
                #pragma unroll
                for (int w = 0; w < 8; w++)
                    s += Part[w * AWF + base_pw[pi][nt]];
                g[nt] = s;
            }
            float gi = g[0] + gxr[pi][0];
            float gf = g[1] + gxr[pi][1];
            float gg = g[2] + gxr[pi][2];
            float go = g[3] + gxr[pi][3];
            float si = 1.f / (1.f + expf(-gi));
            float sf = 1.f / (1.f + expf(-gf));
            float so = 1.f / (1.f + expf(-go));
            float cn = sf * cr[pi] + si * tanhf(gg);
            float hn = so * tanhf(cn);
            int cidx = mm[pi] * HID + j0 + jjv[pi];
            g_c[cidx]   = cn;
            hhout[cidx] = __float2half(hn);
            if (t == S_LEN - 1) hfout[cidx] = hn;   // only final state feeds ar_step
        }
        __syncthreads();

        // ---- grid barrier (R13-proven: single monotonic counter) ----
        if (tid == 0) {
            __threadfence();
            atomicAdd(&g_bar, 1u);
            unsigned target = (unsigned)(t + 1) * GRID;
            while (*(volatile unsigned*)&g_bar < target) { }
            __threadfence();
        }
        __syncthreads();
    }
}

// ============================================================================
// ar_step (unchanged): gates = g_b + h @ Wsum^T ; fp32/tf32 path; writes output
// ============================================================================
__global__ __launch_bounds__(256) void ar_step_kernel(int t, float* __restrict__ out_slot) {
    __shared__ float smem[64 * 36 + 32 * 36];
    float (*As)[36] = reinterpret_cast<float(*)[36]>(smem);
    float (*Bs)[36] = reinterpret_cast<float(*)[36]>(smem + 64 * 36);

    const int tid = threadIdx.x, wid = tid >> 5, lane = tid & 31;
    const int wn = wid & 3;
    const int wm = wid >> 2;
    const int j0 = blockIdx.x * 8;

    const float* __restrict__ h_in  = g_h[t & 1];
    float*       __restrict__ h_out = g_h[(t + 1) & 1];
    const float* __restrict__ W     = g_wsum;

    float c[2][4];
    #pragma unroll
    for (int mt = 0; mt < 2; mt++) {
        int jj = 2 * (lane & 3);
        int n  = wn * HID + j0 + jj;
        float b0 = g_b[n], b1 = g_b[n + 1];
        c[mt][0] = b0; c[mt][1] = b1;
        c[mt][2] = b0; c[mt][3] = b1;
    }

    float4 ra[2], rb;
    auto loadG = [&](int kc) {
        const int k0 = kc * 32;
        #pragma unroll
        for (int i = 0; i < 2; i++) {
            int l = tid + i * 256;
            int r = l >> 3, f = l & 7;
            ra[i] = *reinterpret_cast<const float4*>(h_in + (size_t)r * HID + k0 + f * 4);
        }
        {
            int r = tid >> 3, f = tid & 7;
            int gate = r >> 3, jj2 = r & 7;
            rb = *reinterpret_cast<const float4*>(
                W + (size_t)(gate * HID + j0 + jj2) * HID + k0 + f * 4);
        }
    };

    loadG(0);
    for (int kc = 0; kc < 32; kc++) {
        #pragma unroll
        for (int i = 0; i < 2; i++) {
            int l = tid + i * 256;
            int r = l >> 3, f = l & 7;
            float4 va = ra[i];
            va.x = tfr(va.x); va.y = tfr(va.y); va.z = tfr(va.z); va.w = tfr(va.w);
            *reinterpret_cast<float4*>(&As[r][f * 4]) = va;
        }
        {
            int r = tid >> 3, f = tid & 7;
            float4 vb = rb;
            vb.x = tfr(vb.x); vb.y = tfr(vb.y); vb.z = tfr(vb.z); vb.w = tfr(vb.w);
            *reinterpret_cast<float4*>(&Bs[r][f * 4]) = vb;
        }
        __syncthreads();
        if (kc + 1 < 32) loadG(kc + 1);

        #pragma unroll
        for (int kk = 0; kk < 4; kk++) {
            const int k8 = kk * 8;
            unsigned a[2][4], b[2];
            #pragma unroll
            for (int mt = 0; mt < 2; mt++) {
                int r0 = wm * 32 + mt * 16 + (lane >> 2);
                a[mt][0] = __float_as_uint(As[r0][k8 + (lane & 3)]);
                a[mt][1] = __float_as_uint(As[r0 + 8][k8 + (lane & 3)]);
                a[mt][2] = __float_as_uint(As[r0][k8 + (lane & 3) + 4]);
                a[mt][3] = __float_as_uint(As[r0 + 8][k8 + (lane & 3) + 4]);
            }
            {
                int rb2 = wn * 8 + (lane >> 2);
                b[0] = __float_as_uint(Bs[rb2][k8 + (lane & 3)]);
                b[1] = __float_as_uint(Bs[rb2][k8 + (lane & 3) + 4]);
            }
            #pragma unroll
            for (int mt = 0; mt < 2; mt++)
                mma_tf32(c[mt], a[mt], b);
        }
        __syncthreads();
    }

    float* sg = smem;
    #pragma unroll
    for (int mt = 0; mt < 2; mt++) {
        int row = wm * 32 + mt * 16 + (lane >> 2);
        int jj  = 2 * (lane & 3);
        sg[(wn * 64 + row) * 9 + jj]         = c[mt][0];
        sg[(wn * 64 + row) * 9 + jj + 1]     = c[mt][1];
        sg[(wn * 64 + row + 8) * 9 + jj]     = c[mt][2];
        sg[(wn * 64 + row + 8) * 9 + jj + 1] = c[mt][3];
    }
    __syncthreads();

    for (int q = tid; q < BATCH * 8; q += 256) {
        int m = q >> 3, jj = q & 7;
        float gi = sg[(0 * 64 + m) * 9 + jj];
        float gf = sg[(1 * 64 + m) * 9 + jj];
        float gg = sg[(2 * 64 + m) * 9 + jj];
        float go = sg[(3 * 64 + m) * 9 + jj];
        int cidx = m * HID + j0 + jj;
        float cold = g_c[cidx];
        float si = 1.f / (1.f + expf(-gi));
        float sf = 1.f / (1.f + expf(-gf));
        float so = 1.f / (1.f + expf(-go));
        float cn = sf * cold + si * tanhf(gg);
        float hn = so * tanhf(cn);
        g_c[cidx]      = cn;
        h_out[cidx]    = hn;
        out_slot[cidx] = hn;
    }
}

// ============================================================================
// launch
// ============================================================================
extern "C" void kernel_launch(void* const* d_in, const int* in_sizes, int n_in,
                              void* d_out, int out_size) {
    (void)in_sizes; (void)n_in; (void)out_size;
    const float* x    = (const float*)d_in[0];
    const float* hx0  = (const float*)d_in[1];
    const float* cx0  = (const float*)d_in[2];
    const float* W_ih = (const float*)d_in[3];
    const float* W_hh = (const float*)d_in[4];
    const float* b_ih = (const float*)d_in[5];
    const float* b_hh = (const float*)d_in[6];
    float* out = (float*)d_out;

    static bool attr_set = false;
    if (!attr_set) {
        cudaFuncSetAttribute(persist_kernel,
                             cudaFuncAttributeMaxDynamicSharedMemorySize, SM_TOTAL_P);
        cudaFuncSetAttribute(gemmA_kernel,
                             cudaFuncAttributeMaxDynamicSharedMemorySize, GAH_SMEM);
        attr_set = true;
    }

    prep_kernel<<<(NG * HID + 255) / 256, 256>>>(W_ih, W_hh, b_ih, b_hh, hx0, cx0, x);

    dim3 gA(NG / 128, MTOT / 128);
    gemmA_kernel<<<gA, 256, GAH_SMEM>>>();

    persist_kernel<<<GRID, PTHR, SM_TOTAL_P>>>(W_hh);

    for (int t = S_LEN; t < S_LEN + 2; t++)
        ar_step_kernel<<<HID / 8, 256>>>(t, out + (size_t)(t - S_LEN) * BATCH * HID);
}